// round 4
// baseline (speedup 1.0000x reference)
#include <cuda_runtime.h>

#define LN 1024
#define BATCH 64
#define THREADS 256
#define NCG 16
#define RPT 4
#define ROWS_PER_CTA 64
#define TILES (LN / ROWS_PER_CTA)
#define TOTAL_CTAS (BATCH * TILES)

typedef unsigned long long u64;

__device__ float g_part[TOTAL_CTAS];
__device__ int   g_ctr = 0;

// ---------- f32x2 helpers ----------
__device__ __forceinline__ u64 fma2(u64 a, u64 b, u64 c) {
    u64 d; asm("fma.rn.f32x2 %0, %1, %2, %3;" : "=l"(d) : "l"(a), "l"(b), "l"(c)); return d;
}
__device__ __forceinline__ u64 add2(u64 a, u64 b) {
    u64 d; asm("add.rn.f32x2 %0, %1, %2;" : "=l"(d) : "l"(a), "l"(b)); return d;
}
__device__ __forceinline__ u64 mul2(u64 a, u64 b) {
    u64 d; asm("mul.rn.f32x2 %0, %1, %2;" : "=l"(d) : "l"(a), "l"(b)); return d;
}
__device__ __forceinline__ u64 pack2(float lo, float hi) {
    u64 d; asm("mov.b64 %0, {%1, %2};" : "=l"(d) : "f"(lo), "f"(hi)); return d;
}
__device__ __forceinline__ float2 unpack2(u64 a) {
    float lo, hi; asm("mov.b64 {%0, %1}, %2;" : "=f"(lo), "=f"(hi) : "l"(a));
    return make_float2(lo, hi);
}
__device__ __forceinline__ float fast_sqrt(float a) {
    float r; asm("sqrt.approx.f32 %0, %1;" : "=f"(r) : "f"(a)); return r;
}

#define NEG2_PACKED 0xC0000000C0000000ULL  // (-2.0f, -2.0f)

__global__ __launch_bounds__(THREADS, 3)
void fused_kernel(const float* __restrict__ x, const float* __restrict__ y,
                  float* __restrict__ out) {
    const int b = blockIdx.x, tile = blockIdx.y, tid = threadIdx.x;
    const int warp = tid >> 5, lane = tid & 31;

    __shared__ ulonglong2 sA[LN];       // ( pack(x0,y0), pack(x1,y1) )
    __shared__ ulonglong2 sB[LN];       // ( pack(x2,y2), pack(sqx,sqy) )
    __shared__ int   s_wcnt[8], s_wbase[8], s_nv;
    __shared__ float s_red[8][8];
    __shared__ u64   s_hdr[4];          // S0, S1, S2, SQ packed x/y sums
    __shared__ float wsum[8];
    __shared__ int   s_last;

    // ---- load + transform: thread owns rows [tid*4, tid*4+4) ----
    float X[4][3], Y[4][3], SQX[4], SQY[4];
    int m[4], cnt = 0;
#pragma unroll
    for (int i = 0; i < 4; i++) {
        int l = tid * 4 + i;
        int base = (l * BATCH + b) * 3;
        X[i][0] = x[base]; X[i][1] = x[base + 1]; X[i][2] = x[base + 2];
        Y[i][0] = y[base]; Y[i][1] = y[base + 1]; Y[i][2] = y[base + 2];
        SQX[i] = fmaf(X[i][2], X[i][2], fmaf(X[i][1], X[i][1], X[i][0] * X[i][0]));
        SQY[i] = fmaf(Y[i][2], Y[i][2], fmaf(Y[i][1], Y[i][1], Y[i][0] * Y[i][0]));
        m[i] = ((Y[i][0] + Y[i][1] + Y[i][2]) != 0.0f) ? 1 : 0;
        cnt += m[i];
    }

    // warp inclusive scan of counts (deterministic, l-order stable compaction)
    int inc = cnt;
#pragma unroll
    for (int o = 1; o < 32; o <<= 1) {
        int v = __shfl_up_sync(0xffffffffu, inc, o);
        if (lane >= o) inc += v;
    }
    if (lane == 31) s_wcnt[warp] = inc;

    // masked partial sums: Sx0,Sy0,Sx1,Sy1,Sx2,Sy2,SQx,SQy
    float s[8] = {0, 0, 0, 0, 0, 0, 0, 0};
#pragma unroll
    for (int i = 0; i < 4; i++) {
        if (m[i]) {
            s[0] += X[i][0]; s[1] += Y[i][0];
            s[2] += X[i][1]; s[3] += Y[i][1];
            s[4] += X[i][2]; s[5] += Y[i][2];
            s[6] += SQX[i];  s[7] += SQY[i];
        }
    }
#pragma unroll
    for (int k = 0; k < 8; k++)
#pragma unroll
        for (int o = 16; o > 0; o >>= 1)
            s[k] += __shfl_down_sync(0xffffffffu, s[k], o);
    if (lane == 0)
#pragma unroll
        for (int k = 0; k < 8; k++) s_red[warp][k] = s[k];
    __syncthreads();

    if (tid == 0) {
        int acc = 0;
        for (int w = 0; w < 8; w++) { s_wbase[w] = acc; acc += s_wcnt[w]; }
        s_nv = acc;
        float t[8] = {0, 0, 0, 0, 0, 0, 0, 0};
        for (int w = 0; w < 8; w++)
            for (int k = 0; k < 8; k++) t[k] += s_red[w][k];
        s_hdr[0] = pack2(t[0], t[1]);
        s_hdr[1] = pack2(t[2], t[3]);
        s_hdr[2] = pack2(t[4], t[5]);
        s_hdr[3] = pack2(t[6], t[7]);
    }
    __syncthreads();

    // scatter compacted columns into shared (tail never read: k-loop bounded by nv)
    {
        int pos = s_wbase[warp] + inc - cnt;
#pragma unroll
        for (int i = 0; i < 4; i++) {
            if (m[i]) {
                ulonglong2 qa, qb;
                qa.x = pack2(X[i][0], Y[i][0]);
                qa.y = pack2(X[i][1], Y[i][1]);
                qb.x = pack2(X[i][2], Y[i][2]);
                qb.y = pack2(SQX[i], SQY[i]);
                sA[pos] = qa;
                sB[pos] = qb;
                pos++;
            }
        }
    }
    __syncthreads();

    const int nv = s_nv;
    const u64 S0 = s_hdr[0], S1 = s_hdr[1], S2 = s_hdr[2], SQ = s_hdr[3];
    const u64 NV2 = pack2((float)nv, (float)nv);

    const int cg = tid & (NCG - 1);
    const int rg = tid >> 4;
    const int row0 = tile * ROWS_PER_CTA + rg * RPT;

    float tsum = 0.0f;
    if (row0 < nv) {
        u64 a0[RPT], a1[RPT], a2[RPT], cr[RPT];
        float crTot[RPT], accS[RPT];
#pragma unroll
        for (int r = 0; r < RPT; r++) {
            ulonglong2 qA = sA[row0 + r];   // rows >= nv give garbage but are guarded below
            ulonglong2 qB = sB[row0 + r];
            a0[r] = mul2(qA.x, NEG2_PACKED);
            a1[r] = mul2(qA.y, NEG2_PACKED);
            a2[r] = mul2(qB.x, NEG2_PACKED);
            cr[r] = qB.y;
            // closed form: Sum_j d2(i,j) = nv*sq_i + Sum_j sq_j - 2 * p_i . Sum_j p_j
            u64 dot = fma2(qA.x, S0, fma2(qA.y, S1, mul2(qB.x, S2)));
            u64 Cr  = fma2(dot, NEG2_PACKED, fma2(cr[r], NV2, SQ));
            float2 c = unpack2(Cr);
            crTot[r] = c.x + c.y;
            accS[r]  = 0.0f;
        }

#pragma unroll 2
        for (int k = cg; k < nv; k += NCG) {
            ulonglong2 qA = sA[k];
            ulonglong2 qB = sB[k];
#pragma unroll
            for (int r = 0; r < RPT; r++) {
                u64 t = fma2(a0[r], qA.x, cr[r]);
                t = fma2(a1[r], qA.y, t);
                t = fma2(a2[r], qB.x, t);
                t = add2(t, qB.y);
                float2 d = unpack2(t);               // (d2x, d2y)
                float prod = fmaxf(d.x * d.y, 0.0f);
                accS[r] += fast_sqrt(prod);          // dx*dy
            }
        }

        // crTot added exactly once per row (cg==0); cross term per column-partition
#pragma unroll
        for (int r = 0; r < RPT; r++) {
            if (row0 + r < nv) {
                tsum -= 2.0f * accS[r];
                if (cg == 0) tsum += crTot[r];
            }
        }
    }

    // deterministic block reduce
#pragma unroll
    for (int o = 16; o > 0; o >>= 1)
        tsum += __shfl_down_sync(0xffffffffu, tsum, o);
    if ((tid & 31) == 0) wsum[tid >> 5] = tsum;
    __syncthreads();
    if (tid == 0) {
        float v = 0.0f;
        for (int w = 0; w < 8; w++) v += wsum[w];
        g_part[b * TILES + tile] = v;
        __threadfence();
        int old = atomicAdd(&g_ctr, 1);
        s_last = (old == TOTAL_CTAS - 1) ? 1 : 0;
    }
    __syncthreads();

    // ---- last CTA performs the final reduction (deterministic read order) ----
    if (s_last) {
        float v = 0.0f;
        if (tid < BATCH) {
            float ssum = 0.0f;
            for (int t = 0; t < TILES; t++)
                ssum += __ldcg(&g_part[tid * TILES + t]);
            v = fast_sqrt(fmaxf(ssum, 0.0f));
        }
        // reduce 64 lanes -> scalar (2 warps)
#pragma unroll
        for (int o = 16; o > 0; o >>= 1)
            v += __shfl_down_sync(0xffffffffu, v, o);
        if ((tid & 31) == 0) wsum[tid >> 5] = v;
        __syncthreads();
        if (tid == 0) {
            const float denom = 723.3699523f;  // sqrt(1024^2/2 - 1024)
            out[0] = (wsum[0] + wsum[1]) / denom / (float)BATCH;
            g_ctr = 0;                          // reset for next graph replay
        }
    }
}

extern "C" void kernel_launch(void* const* d_in, const int* in_sizes, int n_in,
                              void* d_out, int out_size) {
    const float* x = (const float*)d_in[0];
    const float* y = (const float*)d_in[1];
    float* out = (float*)d_out;
    (void)in_sizes; (void)n_in; (void)out_size;

    dim3 grid(BATCH, TILES);
    fused_kernel<<<grid, THREADS>>>(x, y, out);
}

// round 5
// speedup vs baseline: 1.1837x; 1.1837x over previous
#include <cuda_runtime.h>

#define LN 1024
#define BATCH 64
#define THREADS 256
#define NCG 16
#define RPT 4
#define ROWS_PER_CTA 64
#define TILES (LN / ROWS_PER_CTA)
#define TOTAL_CTAS (BATCH * TILES)

typedef unsigned long long u64;

// Scratch (device globals; no runtime allocation).
__device__ ulonglong2 g_colA[BATCH][LN];  // ( pack(x0,y0), pack(x1,y1) )
__device__ ulonglong2 g_colB[BATCH][LN];  // ( pack(x2,y2), pack(sqx,sqy) )
__device__ float      g_msk[BATCH][LN];   // 1.0 if y-row observed else 0.0
__device__ float      g_part[TOTAL_CTAS];
__device__ int        g_ctr = 0;

// ---------- f32x2 helpers ----------
__device__ __forceinline__ u64 fma2(u64 a, u64 b, u64 c) {
    u64 d; asm("fma.rn.f32x2 %0, %1, %2, %3;" : "=l"(d) : "l"(a), "l"(b), "l"(c)); return d;
}
__device__ __forceinline__ u64 add2(u64 a, u64 b) {
    u64 d; asm("add.rn.f32x2 %0, %1, %2;" : "=l"(d) : "l"(a), "l"(b)); return d;
}
__device__ __forceinline__ u64 mul2(u64 a, u64 b) {
    u64 d; asm("mul.rn.f32x2 %0, %1, %2;" : "=l"(d) : "l"(a), "l"(b)); return d;
}
__device__ __forceinline__ u64 pack2(float lo, float hi) {
    u64 d; asm("mov.b64 %0, {%1, %2};" : "=l"(d) : "f"(lo), "f"(hi)); return d;
}
__device__ __forceinline__ float2 unpack2(u64 a) {
    float lo, hi; asm("mov.b64 {%0, %1}, %2;" : "=f"(lo), "=f"(hi) : "l"(a));
    return make_float2(lo, hi);
}
__device__ __forceinline__ float fast_sqrt(float a) {
    float r; asm("sqrt.approx.f32 %0, %1;" : "=f"(r) : "f"(a)); return r;
}

#define NEG2_PACKED 0xC0000000C0000000ULL  // (-2.0f, -2.0f)

// ---------- pre-kernel: pure transform, fully coalesced, no scan ----------
// grid = LN/4 = 256 CTAs, 256 threads; thread <-> (l, b), b-major for coalescing.
__global__ __launch_bounds__(THREADS)
void pre_kernel(const float* __restrict__ x, const float* __restrict__ y) {
    const int tid = threadIdx.x;
    const int b  = tid & (BATCH - 1);
    const int dl = tid >> 6;
    const int l  = blockIdx.x * 4 + dl;
    const int base = (l * BATCH + b) * 3;

    float x0 = x[base], x1 = x[base + 1], x2 = x[base + 2];
    float y0 = y[base], y1 = y[base + 1], y2 = y[base + 2];
    float sqx = fmaf(x2, x2, fmaf(x1, x1, x0 * x0));
    float sqy = fmaf(y2, y2, fmaf(y1, y1, y0 * y0));
    float m = ((y0 + y1 + y2) != 0.0f) ? 1.0f : 0.0f;

    ulonglong2 qa, qb;
    qa.x = pack2(x0, y0); qa.y = pack2(x1, y1);
    qb.x = pack2(x2, y2); qb.y = pack2(sqx, sqy);
    g_colA[b][l] = qa;
    g_colB[b][l] = qb;
    g_msk[b][l]  = m;
}

// ---------- pair kernel: masked cross-term, header computed in prologue ----------
__global__ __launch_bounds__(THREADS, 4)
void pair_kernel(float* __restrict__ out) {
    const int b = blockIdx.x, tile = blockIdx.y, tid = threadIdx.x;
    const int warp = tid >> 5, lane = tid & 31;

    __shared__ ulonglong2 sA[LN];
    __shared__ ulonglong2 sB[LN];
    __shared__ float smsk[LN];
    __shared__ float s_red[8][9];
    __shared__ u64   s_hdr[4];
    __shared__ float s_nvf;
    __shared__ float wsum[8];
    __shared__ int   s_last;

    // ---- fill smem (coalesced 16B loads) + masked header sums ----
    float s[9] = {0, 0, 0, 0, 0, 0, 0, 0, 0};
#pragma unroll
    for (int i = tid; i < LN; i += THREADS) {
        ulonglong2 qa = g_colA[b][i];
        ulonglong2 qb = g_colB[b][i];
        float m = g_msk[b][i];
        sA[i] = qa; sB[i] = qb; smsk[i] = m;
        float2 p0 = unpack2(qa.x), p1 = unpack2(qa.y);
        float2 p2 = unpack2(qb.x), pq = unpack2(qb.y);
        s[0] = fmaf(m, p0.x, s[0]); s[1] = fmaf(m, p0.y, s[1]);
        s[2] = fmaf(m, p1.x, s[2]); s[3] = fmaf(m, p1.y, s[3]);
        s[4] = fmaf(m, p2.x, s[4]); s[5] = fmaf(m, p2.y, s[5]);
        s[6] = fmaf(m, pq.x, s[6]); s[7] = fmaf(m, pq.y, s[7]);
        s[8] += m;
    }
#pragma unroll
    for (int k = 0; k < 9; k++)
#pragma unroll
        for (int o = 16; o > 0; o >>= 1)
            s[k] += __shfl_down_sync(0xffffffffu, s[k], o);
    if (lane == 0)
#pragma unroll
        for (int k = 0; k < 9; k++) s_red[warp][k] = s[k];
    __syncthreads();
    if (tid == 0) {
        float t[9] = {0, 0, 0, 0, 0, 0, 0, 0, 0};
        for (int w = 0; w < 8; w++)
            for (int k = 0; k < 9; k++) t[k] += s_red[w][k];
        s_hdr[0] = pack2(t[0], t[1]);
        s_hdr[1] = pack2(t[2], t[3]);
        s_hdr[2] = pack2(t[4], t[5]);
        s_hdr[3] = pack2(t[6], t[7]);
        s_nvf = t[8];
    }
    __syncthreads();

    const u64 S0 = s_hdr[0], S1 = s_hdr[1], S2 = s_hdr[2], SQ = s_hdr[3];
    const u64 NV2 = pack2(s_nvf, s_nvf);

    const int cg = tid & (NCG - 1);
    const int rg = tid >> 4;
    const int row0 = tile * ROWS_PER_CTA + rg * RPT;

    // ---- row coefficients ----
    u64 a0[RPT], a1[RPT], a2[RPT], cr[RPT];
    float crTot[RPT], accS[RPT], rmask[RPT];
    float anyrow = 0.0f;
#pragma unroll
    for (int r = 0; r < RPT; r++) {
        ulonglong2 qA = sA[row0 + r];
        ulonglong2 qB = sB[row0 + r];
        a0[r] = mul2(qA.x, NEG2_PACKED);
        a1[r] = mul2(qA.y, NEG2_PACKED);
        a2[r] = mul2(qB.x, NEG2_PACKED);
        cr[r] = qB.y;
        // closed form: Sum_j mj*d2(i,j) = nv*sq_i + SQsum - 2 * p_i . S   (packed x/y)
        u64 dot = fma2(qA.x, S0, fma2(qA.y, S1, mul2(qB.x, S2)));
        u64 Cr  = fma2(dot, NEG2_PACKED, fma2(cr[r], NV2, SQ));
        float2 c = unpack2(Cr);
        crTot[r] = c.x + c.y;
        accS[r]  = 0.0f;
        rmask[r] = smsk[row0 + r];
        anyrow  += rmask[r];
    }

    float tsum = 0.0f;
    if (anyrow != 0.0f) {
#pragma unroll 2
        for (int k = cg; k < LN; k += NCG) {
            ulonglong2 qA = sA[k];
            ulonglong2 qB = sB[k];
            float mj = smsk[k];
#pragma unroll
            for (int r = 0; r < RPT; r++) {
                u64 t = fma2(a0[r], qA.x, cr[r]);
                t = fma2(a1[r], qA.y, t);
                t = fma2(a2[r], qB.x, t);
                t = add2(t, qB.y);
                float2 d = unpack2(t);               // (d2x, d2y)
                float prod = fmaxf(d.x * d.y, 0.0f);
                accS[r] = fmaf(mj, fast_sqrt(prod), accS[r]);  // mask folded, free
            }
        }
        // crTot once per row (cg==0); cross term per column-partition; row mask outside
#pragma unroll
        for (int r = 0; r < RPT; r++) {
            float c = -2.0f * accS[r];
            if (cg == 0) c += crTot[r];
            tsum = fmaf(rmask[r], c, tsum);
        }
    }

    // ---- deterministic block reduce ----
#pragma unroll
    for (int o = 16; o > 0; o >>= 1)
        tsum += __shfl_down_sync(0xffffffffu, tsum, o);
    if ((tid & 31) == 0) wsum[tid >> 5] = tsum;
    __syncthreads();
    if (tid == 0) {
        float v = 0.0f;
        for (int w = 0; w < 8; w++) v += wsum[w];
        g_part[b * TILES + tile] = v;
        __threadfence();
        int old = atomicAdd(&g_ctr, 1);
        s_last = (old == TOTAL_CTAS - 1) ? 1 : 0;
    }
    __syncthreads();

    // ---- last CTA: final reduction (deterministic fixed-order reads) ----
    if (s_last) {
        float v = 0.0f;
        if (tid < BATCH) {
            float ssum = 0.0f;
            for (int t = 0; t < TILES; t++)
                ssum += __ldcg(&g_part[tid * TILES + t]);
            v = fast_sqrt(fmaxf(ssum, 0.0f));
        }
#pragma unroll
        for (int o = 16; o > 0; o >>= 1)
            v += __shfl_down_sync(0xffffffffu, v, o);
        if ((tid & 31) == 0) wsum[tid >> 5] = v;
        __syncthreads();
        if (tid == 0) {
            const float denom = 723.3699523f;  // sqrt(1024^2/2 - 1024)
            out[0] = (wsum[0] + wsum[1]) / denom / (float)BATCH;
            g_ctr = 0;                          // reset for next graph replay
        }
    }
}

extern "C" void kernel_launch(void* const* d_in, const int* in_sizes, int n_in,
                              void* d_out, int out_size) {
    const float* x = (const float*)d_in[0];
    const float* y = (const float*)d_in[1];
    float* out = (float*)d_out;
    (void)in_sizes; (void)n_in; (void)out_size;

    pre_kernel<<<LN / 4, THREADS>>>(x, y);
    dim3 grid(BATCH, TILES);
    pair_kernel<<<grid, THREADS>>>(out);
}